// round 1
// baseline (speedup 1.0000x reference)
#include <cuda_runtime.h>
#include <math.h>

// Problem constants
#define BB      8
#define HH      384
#define WW      384
#define NN      96
#define NSEG    (NN - 1)
#define HWSZ    (HH * WW)
#define STEPSZ  0.1f
#define ALPHA_C 0.01f
#define BETA_C  0.01f
#define NSTEPS  50
#define NSTEPS_W 10
#define DMAX_C  15.0f
#define EXTF    10.0f

// Render grid: 147456 px / 256 = 576 blocks per image
#define RENDER_TPB    256
#define BLKS_PER_IMG  (HWSZ / RENDER_TPB)   // 576
#define RENDER_BLKS   (BB * BLKS_PER_IMG)   // 4608

// ---------------- device scratch (no allocations allowed) ----------------
__device__ float g_g [BB * 2 * HWSZ];   // gimg  (grad of pred)     * 10
__device__ float g_gw[BB * 2 * HWSZ];   // gimgW (grad of |pred|)   * 10
__device__ float g_segs[BB * NSEG * 9]; // per-segment precomputed data
__device__ float g_part[RENDER_BLKS];   // per-block partial loss sums

// ---------------- kernel 1: 7x7 conv (SAME, zero pad), 2 filters, x + |x| --
#define TILE 32
#define RAD  3
#define SH   (TILE + 2 * RAD)  // 38

__global__ void conv_kernel(const float* __restrict__ pred,
                            const float* __restrict__ fltr) {
    __shared__ float s_in[SH][SH + 1];
    __shared__ float s_f[2][49];
    const int b  = blockIdx.z;
    const int tx = threadIdx.x, ty = threadIdx.y;
    const int x0 = blockIdx.x * TILE, y0 = blockIdx.y * TILE;
    const int tid = ty * TILE + tx;

    if (tid < 98) s_f[tid / 49][tid % 49] = fltr[tid];

    const float* img = pred + (size_t)b * HWSZ;
    for (int i = tid; i < SH * SH; i += TILE * TILE) {
        int sy = i / SH, sx = i % SH;
        int gy = y0 + sy - RAD, gx = x0 + sx - RAD;
        float v = 0.0f;
        if (gy >= 0 && gy < HH && gx >= 0 && gx < WW) v = img[gy * WW + gx];
        s_in[sy][sx] = v;
    }
    __syncthreads();

    float a00 = 0.f, a01 = 0.f, a10 = 0.f, a11 = 0.f;
#pragma unroll
    for (int dy = 0; dy < 7; dy++) {
#pragma unroll
        for (int dx = 0; dx < 7; dx++) {
            float p  = s_in[ty + dy][tx + dx];
            float ap = fabsf(p);
            float f0 = s_f[0][dy * 7 + dx];
            float f1 = s_f[1][dy * 7 + dx];
            a00 = fmaf(p,  f0, a00);
            a01 = fmaf(p,  f1, a01);
            a10 = fmaf(ap, f0, a10);
            a11 = fmaf(ap, f1, a11);
        }
    }
    const int gy = y0 + ty, gx = x0 + tx;
    const size_t base = (size_t)b * 2 * HWSZ + (size_t)gy * WW + gx;
    g_g [base]        = a00 * EXTF;
    g_g [base + HWSZ] = a01 * EXTF;
    g_gw[base]        = a10 * EXTF;
    g_gw[base + HWSZ] = a11 * EXTF;
}

// ---------------- bilinear interp of 2-channel image ----------------------
__device__ __forceinline__ void interp2(const float* __restrict__ img,
                                        float py, float px,
                                        float& v0, float& v1) {
    float y = fminf(fmaxf(py, 0.0f), (float)(HH - 1));
    float x = fminf(fmaxf(px, 0.0f), (float)(WW - 1));
    float y0f = floorf(y), x0f = floorf(x);
    int y0 = (int)y0f, x0 = (int)x0f;
    int y1 = min(y0 + 1, HH - 1);
    int x1 = min(x0 + 1, WW - 1);
    float wy = y - y0f, wx = x - x0f;
    float w00 = (1.0f - wy) * (1.0f - wx);
    float w01 = (1.0f - wy) * wx;
    float w10 = wy * (1.0f - wx);
    float w11 = wy * wx;
    const float* c0 = img;
    const float* c1 = img + HWSZ;
    int i00 = y0 * WW + x0, i01 = y0 * WW + x1;
    int i10 = y1 * WW + x0, i11 = y1 * WW + x1;
    v0 = c0[i00] * w00 + c0[i01] * w01 + c0[i10] * w10 + c0[i11] * w11;
    v1 = c1[i00] * w00 + c1[i01] * w01 + c1[i10] * w10 + c1[i11] * w11;
}

// ---------------- kernel 2: snake evolution + width fit + segment precompute
__global__ void snake_kernel(const float* __restrict__ nodes,
                             const float* __restrict__ widths) {
    const int b = blockIdx.x;
    const int i = threadIdx.x;
    const bool act = (i < NN);

    __shared__ float xs [NN][2];
    __shared__ float d2s[NN][2];
    __shared__ float wsh[NN];

    const float* g  = g_g  + (size_t)b * 2 * HWSZ;
    const float* gw = g_gw + (size_t)b * 2 * HWSZ;

    float xy = 0.f, xx = 0.f;
    if (act) {
        xy = nodes[((size_t)b * NN + i) * 2 + 0];
        xx = nodes[((size_t)b * NN + i) * 2 + 1];
        xs[i][0] = xy; xs[i][1] = xx;
    }
    __syncthreads();

    // --- position steps ---
    for (int s = 0; s < NSTEPS; s++) {
        float fe0 = 0.f, fe1 = 0.f, d20 = 0.f, d21 = 0.f;
        if (act) {
            interp2(g, xy, xx, fe0, fe1);
            int im = max(i - 1, 0), ip = min(i + 1, NN - 1);
            d20 = xs[im][0] - 2.0f * xy + xs[ip][0];
            d21 = xs[im][1] - 2.0f * xx + xs[ip][1];
            d2s[i][0] = d20; d2s[i][1] = d21;
        }
        __syncthreads();
        if (act) {
            int im = max(i - 1, 0), ip = min(i + 1, NN - 1);
            float d40 = d2s[im][0] - 2.0f * d20 + d2s[ip][0];
            float d41 = d2s[im][1] - 2.0f * d21 + d2s[ip][1];
            xy += STEPSZ * (ALPHA_C * d20 - BETA_C * d40 + fe0);
            xx += STEPSZ * (ALPHA_C * d21 - BETA_C * d41 + fe1);
            xs[i][0] = xy; xs[i][1] = xx;
        }
        __syncthreads();
    }

    // --- tangent / normal + width steps (per-node independent) ---
    if (act) {
        float t0, t1;
        if (i == 0)            { t0 = xs[1][0] - xs[0][0];           t1 = xs[1][1] - xs[0][1]; }
        else if (i == NN - 1)  { t0 = xs[NN-1][0] - xs[NN-2][0];     t1 = xs[NN-1][1] - xs[NN-2][1]; }
        else                   { t0 = 0.5f * (xs[i+1][0] - xs[i-1][0]); t1 = 0.5f * (xs[i+1][1] - xs[i-1][1]); }
        float n0 = -t1, n1 = t0;
        float nrm = sqrtf(n0 * n0 + n1 * n1) + 1e-6f;
        n0 /= nrm; n1 /= nrm;

        float w = widths[(size_t)b * NN + i];
        for (int s = 0; s < NSTEPS_W; s++) {
            float gp0, gp1, gm0, gm1;
            interp2(gw, xy + w * n0, xx + w * n1, gp0, gp1);
            interp2(gw, xy - w * n0, xx - w * n1, gm0, gm1);
            float f = 0.5f * ((gp0 * n0 + gp1 * n1) - (gm0 * n0 + gm1 * n1));
            w = fmaxf(w + STEPSZ * f, 0.5f);
        }
        wsh[i] = w;
    }
    __syncthreads();

    // --- per-segment precompute: {aby,abx,aab,invden,den,-2ay,-2ax,a2,ws} ---
    if (i < NSEG) {
        float ay = xs[i][0],   ax = xs[i][1];
        float by = xs[i+1][0], bx = xs[i+1][1];
        float aby = by - ay, abx = bx - ax;
        float den = aby * aby + abx * abx + 1e-8f;
        float aab = ay * aby + ax * abx;
        float a2  = ay * ay + ax * ax;
        float wsg = 0.5f * (wsh[i] + wsh[i + 1]);
        float* sp = g_segs + ((size_t)b * NSEG + i) * 9;
        sp[0] = aby; sp[1] = abx; sp[2] = aab;
        sp[3] = 1.0f / den; sp[4] = den;
        sp[5] = -2.0f * ay; sp[6] = -2.0f * ax;
        sp[7] = a2; sp[8] = wsg;
    }
}

// ---------------- kernel 3: render dmap + squared-error partial sums -------
__global__ void __launch_bounds__(RENDER_TPB)
render_kernel(const float* __restrict__ pred) {
    __shared__ float segs[NSEG * 9];
    __shared__ float red[RENDER_TPB];

    const int tid = threadIdx.x;
    const int b   = blockIdx.x / BLKS_PER_IMG;
    const int pix = (blockIdx.x % BLKS_PER_IMG) * RENDER_TPB + tid;

    const float* sp = g_segs + (size_t)b * NSEG * 9;
    for (int j = tid; j < NSEG * 9; j += RENDER_TPB) segs[j] = sp[j];
    __syncthreads();

    const float fy = (float)(pix / WW);
    const float fx = (float)(pix % WW);
    const float p2 = fy * fy + fx * fx;

    float m = 3.0e38f;
#pragma unroll 5
    for (int s = 0; s < NSEG; s++) {
        const float* q = &segs[s * 9];
        float aby = q[0], abx = q[1], aab = q[2];
        float invd = q[3], den = q[4];
        float m2ay = q[5], m2ax = q[6], a2 = q[7], wsg = q[8];

        float dotpa = fmaf(fy, aby, fmaf(fx, abx, -aab));
        float t = fminf(fmaxf(dotpa * invd, 0.0f), 1.0f);
        float pa2 = p2 + fmaf(fy, m2ay, fmaf(fx, m2ax, a2));
        float dd = fmaf(t, fmaf(t, den, -2.0f * dotpa), pa2);
        float d = sqrtf(fmaxf(dd, 0.0f));
        m = fminf(m, d - wsg);
    }
    // min_i max(d-ws,0) == max(min_i(d-ws),0); then clip at DMAX
    float dmap = fminf(fmaxf(m, 0.0f), DMAX_C);
    float diff = pred[(size_t)b * HWSZ + pix] - dmap;
    float v = diff * diff;

    red[tid] = v;
    __syncthreads();
#pragma unroll
    for (int s = RENDER_TPB / 2; s > 0; s >>= 1) {
        if (tid < s) red[tid] += red[tid + s];
        __syncthreads();
    }
    if (tid == 0) g_part[blockIdx.x] = red[0];
}

// ---------------- kernel 4: deterministic final reduction ------------------
__global__ void reduce_kernel(float* __restrict__ out) {
    __shared__ double sd[256];
    const int tid = threadIdx.x;
    double a = 0.0;
    for (int i = tid; i < RENDER_BLKS; i += 256) a += (double)g_part[i];
    sd[tid] = a;
    __syncthreads();
#pragma unroll
    for (int s = 128; s > 0; s >>= 1) {
        if (tid < s) sd[tid] += sd[tid + s];
        __syncthreads();
    }
    if (tid == 0) out[0] = (float)(sd[0] / (double)((size_t)BB * HWSZ));
}

// ---------------- launcher --------------------------------------------------
extern "C" void kernel_launch(void* const* d_in, const int* in_sizes, int n_in,
                              void* d_out, int out_size) {
    const float* pred   = (const float*)d_in[0];  // (8,1,384,384)
    const float* nodes  = (const float*)d_in[1];  // (8,96,2)
    const float* widths = (const float*)d_in[2];  // (8,96)
    const float* fltr   = (const float*)d_in[3];  // (2,1,7,7)
    float* out = (float*)d_out;

    dim3 cgrid(WW / TILE, HH / TILE, BB);
    dim3 cblk(TILE, TILE);
    conv_kernel<<<cgrid, cblk>>>(pred, fltr);

    snake_kernel<<<BB, 128>>>(nodes, widths);

    render_kernel<<<RENDER_BLKS, RENDER_TPB>>>(pred);

    reduce_kernel<<<1, 256>>>(out);
}

// round 2
// speedup vs baseline: 2.4277x; 2.4277x over previous
#include <cuda_runtime.h>
#include <math.h>

// Problem constants
#define BB      8
#define HH      384
#define WW      384
#define NN      96
#define NSEG    (NN - 1)
#define HWSZ    (HH * WW)
#define STEPSZ  0.1f
#define ALPHA_C 0.01f
#define BETA_C  0.01f
#define NSTEPS  50
#define NSTEPS_W 10
#define DMAX_C  15.0f
#define EXTF    10.0f

// Render: 16x16 pixel tiles, 256 threads, 1 px/thread
#define TDIM          16
#define RENDER_TPB    256
#define TILES_X       (WW / TDIM)              // 24
#define TILES_Y       (HH / TDIM)              // 24
#define BLKS_PER_IMG  (TILES_X * TILES_Y)      // 576
#define RENDER_BLKS   (BB * BLKS_PER_IMG)      // 4608
// half-diagonal of pixel-center extent (±7.5,±7.5) + float-rounding safety
#define TILE_RAD      10.80f

// ---------------- device scratch (no allocations allowed) ----------------
__device__ float  g_g [BB * 2 * HWSZ];    // gimg  * 10
__device__ float  g_gw[BB * 2 * HWSZ];    // gimgW * 10
__device__ float4 g_segs[BB * NSEG * 3];  // per-segment data, 3 x float4
__device__ float  g_part[RENDER_BLKS];    // per-block partial sums
__device__ unsigned int g_cnt = 0;        // last-block counter (self-resetting)

// ---------------- kernel 1: 7x7 conv (SAME, zero pad), 2 filters, x + |x| --
#define TILE 32
#define RAD  3
#define SH   (TILE + 2 * RAD)  // 38

__global__ void conv_kernel(const float* __restrict__ pred,
                            const float* __restrict__ fltr) {
    __shared__ float s_in[SH][SH + 1];
    __shared__ float s_f[2][49];
    const int b  = blockIdx.z;
    const int tx = threadIdx.x, ty = threadIdx.y;
    const int x0 = blockIdx.x * TILE, y0 = blockIdx.y * TILE;
    const int tid = ty * TILE + tx;

    if (tid < 98) s_f[tid / 49][tid % 49] = fltr[tid];

    const float* img = pred + (size_t)b * HWSZ;
    for (int i = tid; i < SH * SH; i += TILE * TILE) {
        int sy = i / SH, sx = i % SH;
        int gy = y0 + sy - RAD, gx = x0 + sx - RAD;
        float v = 0.0f;
        if (gy >= 0 && gy < HH && gx >= 0 && gx < WW) v = img[gy * WW + gx];
        s_in[sy][sx] = v;
    }
    __syncthreads();

    float a00 = 0.f, a01 = 0.f, a10 = 0.f, a11 = 0.f;
#pragma unroll
    for (int dy = 0; dy < 7; dy++) {
#pragma unroll
        for (int dx = 0; dx < 7; dx++) {
            float p  = s_in[ty + dy][tx + dx];
            float ap = fabsf(p);
            float f0 = s_f[0][dy * 7 + dx];
            float f1 = s_f[1][dy * 7 + dx];
            a00 = fmaf(p,  f0, a00);
            a01 = fmaf(p,  f1, a01);
            a10 = fmaf(ap, f0, a10);
            a11 = fmaf(ap, f1, a11);
        }
    }
    const int gy = y0 + ty, gx = x0 + tx;
    const size_t base = (size_t)b * 2 * HWSZ + (size_t)gy * WW + gx;
    g_g [base]        = a00 * EXTF;
    g_g [base + HWSZ] = a01 * EXTF;
    g_gw[base]        = a10 * EXTF;
    g_gw[base + HWSZ] = a11 * EXTF;
}

// ---------------- bilinear interp of 2-channel image ----------------------
__device__ __forceinline__ void interp2(const float* __restrict__ img,
                                        float py, float px,
                                        float& v0, float& v1) {
    float y = fminf(fmaxf(py, 0.0f), (float)(HH - 1));
    float x = fminf(fmaxf(px, 0.0f), (float)(WW - 1));
    float y0f = floorf(y), x0f = floorf(x);
    int y0 = (int)y0f, x0 = (int)x0f;
    int y1 = min(y0 + 1, HH - 1);
    int x1 = min(x0 + 1, WW - 1);
    float wy = y - y0f, wx = x - x0f;
    float w00 = (1.0f - wy) * (1.0f - wx);
    float w01 = (1.0f - wy) * wx;
    float w10 = wy * (1.0f - wx);
    float w11 = wy * wx;
    const float* c0 = img;
    const float* c1 = img + HWSZ;
    int i00 = y0 * WW + x0, i01 = y0 * WW + x1;
    int i10 = y1 * WW + x0, i11 = y1 * WW + x1;
    v0 = c0[i00] * w00 + c0[i01] * w01 + c0[i10] * w10 + c0[i11] * w11;
    v1 = c1[i00] * w00 + c1[i01] * w01 + c1[i10] * w10 + c1[i11] * w11;
}

// ---------------- kernel 2: snake evolution + width fit + segment precompute
__global__ void snake_kernel(const float* __restrict__ nodes,
                             const float* __restrict__ widths) {
    const int b = blockIdx.x;
    const int i = threadIdx.x;
    const bool act = (i < NN);

    __shared__ float xs [NN][2];
    __shared__ float d2s[NN][2];
    __shared__ float wsh[NN];

    const float* g  = g_g  + (size_t)b * 2 * HWSZ;
    const float* gw = g_gw + (size_t)b * 2 * HWSZ;

    float xy = 0.f, xx = 0.f;
    if (act) {
        xy = nodes[((size_t)b * NN + i) * 2 + 0];
        xx = nodes[((size_t)b * NN + i) * 2 + 1];
        xs[i][0] = xy; xs[i][1] = xx;
    }
    __syncthreads();

    // --- position steps ---
    for (int s = 0; s < NSTEPS; s++) {
        float fe0 = 0.f, fe1 = 0.f, d20 = 0.f, d21 = 0.f;
        if (act) {
            interp2(g, xy, xx, fe0, fe1);
            int im = max(i - 1, 0), ip = min(i + 1, NN - 1);
            d20 = xs[im][0] - 2.0f * xy + xs[ip][0];
            d21 = xs[im][1] - 2.0f * xx + xs[ip][1];
            d2s[i][0] = d20; d2s[i][1] = d21;
        }
        __syncthreads();
        if (act) {
            int im = max(i - 1, 0), ip = min(i + 1, NN - 1);
            float d40 = d2s[im][0] - 2.0f * d20 + d2s[ip][0];
            float d41 = d2s[im][1] - 2.0f * d21 + d2s[ip][1];
            xy += STEPSZ * (ALPHA_C * d20 - BETA_C * d40 + fe0);
            xx += STEPSZ * (ALPHA_C * d21 - BETA_C * d41 + fe1);
            xs[i][0] = xy; xs[i][1] = xx;
        }
        __syncthreads();
    }

    // --- tangent / normal + width steps ---
    if (act) {
        float t0, t1;
        if (i == 0)            { t0 = xs[1][0] - xs[0][0];           t1 = xs[1][1] - xs[0][1]; }
        else if (i == NN - 1)  { t0 = xs[NN-1][0] - xs[NN-2][0];     t1 = xs[NN-1][1] - xs[NN-2][1]; }
        else                   { t0 = 0.5f * (xs[i+1][0] - xs[i-1][0]); t1 = 0.5f * (xs[i+1][1] - xs[i-1][1]); }
        float n0 = -t1, n1 = t0;
        float nrm = sqrtf(n0 * n0 + n1 * n1) + 1e-6f;
        n0 /= nrm; n1 /= nrm;

        float w = widths[(size_t)b * NN + i];
        for (int s = 0; s < NSTEPS_W; s++) {
            float gp0, gp1, gm0, gm1;
            interp2(gw, xy + w * n0, xx + w * n1, gp0, gp1);
            interp2(gw, xy - w * n0, xx - w * n1, gm0, gm1);
            float f = 0.5f * ((gp0 * n0 + gp1 * n1) - (gm0 * n0 + gm1 * n1));
            w = fmaxf(w + STEPSZ * f, 0.5f);
        }
        wsh[i] = w;
    }
    __syncthreads();

    // --- per-segment precompute: 3 x float4 per segment ---
    if (i < NSEG) {
        float ay = xs[i][0],   ax = xs[i][1];
        float by = xs[i+1][0], bx = xs[i+1][1];
        float aby = by - ay, abx = bx - ax;
        float den = aby * aby + abx * abx + 1e-8f;
        float aab = ay * aby + ax * abx;
        float a2  = ay * ay + ax * ax;
        float wsg = 0.5f * (wsh[i] + wsh[i + 1]);
        float4* sp = g_segs + ((size_t)b * NSEG + i) * 3;
        sp[0] = make_float4(aby, abx, aab, 1.0f / den);
        sp[1] = make_float4(den, -2.0f * ay, -2.0f * ax, a2);
        sp[2] = make_float4(wsg, 0.f, 0.f, 0.f);
    }
}

// ---------------- kernel 3: culled render + loss + fused final reduction ---
__global__ void __launch_bounds__(RENDER_TPB)
render_kernel(const float* __restrict__ pred, float* __restrict__ out) {
    __shared__ float4 ksA[NSEG];     // (aby,abx,aab,invd)
    __shared__ float4 ksB[NSEG];     // (den,-2ay,-2ax,a2)
    __shared__ float  ksW[NSEG];     // wsg
    __shared__ int    s_nk;
    __shared__ int    s_last;
    __shared__ float  wsum[RENDER_TPB / 32];
    __shared__ double sd[RENDER_TPB];

    const int tid = threadIdx.x;
    const int bx = blockIdx.x, by = blockIdx.y, b = blockIdx.z;
    const int bid = (b * TILES_Y + by) * TILES_X + bx;

    if (tid == 0) s_nk = 0;
    __syncthreads();

    // ---- cull phase: one segment per thread against tile center ----
    const float cy = (float)(by * TDIM) + 7.5f;
    const float cx = (float)(bx * TDIM) + 7.5f;
    if (tid < NSEG) {
        const float4* sp = g_segs + ((size_t)b * NSEG + tid) * 3;
        float4 qa = sp[0];
        float4 qb = sp[1];
        float  wsg = sp[2].x;
        float dotpa = fmaf(cy, qa.x, fmaf(cx, qa.y, -qa.z));
        float t = fminf(fmaxf(dotpa * qa.w, 0.0f), 1.0f);
        float pa2 = fmaf(cy, cy, cx * cx) + fmaf(cy, qb.y, fmaf(cx, qb.z, qb.w));
        float dd = fmaf(t, fmaf(t, qb.x, -2.0f * dotpa), pa2);
        float dc = sqrtf(fmaxf(dd, 0.0f));
        if (dc - wsg <= DMAX_C + TILE_RAD) {
            int slot = atomicAdd(&s_nk, 1);
            ksA[slot] = qa;
            ksB[slot] = qb;
            ksW[slot] = wsg;
        }
    }
    __syncthreads();
    const int nk = s_nk;

    // ---- per-pixel evaluation ----
    const int py = by * TDIM + (tid >> 4);
    const int px = bx * TDIM + (tid & 15);
    const float fy = (float)py;
    const float fx = (float)px;
    const float p2 = fy * fy + fx * fx;

    float m = 3.0e38f;
    for (int s = 0; s < nk; s++) {
        float4 qa = ksA[s];
        float4 qb = ksB[s];
        float dotpa = fmaf(fy, qa.x, fmaf(fx, qa.y, -qa.z));
        float t = fminf(fmaxf(dotpa * qa.w, 0.0f), 1.0f);
        float pa2 = p2 + fmaf(fy, qb.y, fmaf(fx, qb.z, qb.w));
        float dd = fmaf(t, fmaf(t, qb.x, -2.0f * dotpa), pa2);
        float d = sqrtf(fmaxf(dd, 0.0f));
        m = fminf(m, d - ksW[s]);
    }
    // min_i max(d-ws,0) == max(min_i(d-ws),0); then clip at DMAX
    float dmap = fminf(fmaxf(m, 0.0f), DMAX_C);
    float diff = pred[(size_t)b * HWSZ + (size_t)py * WW + px] - dmap;
    float v = diff * diff;

    // ---- block reduce (warp shuffles + shared) ----
#pragma unroll
    for (int o = 16; o > 0; o >>= 1) v += __shfl_down_sync(0xffffffffu, v, o);
    if ((tid & 31) == 0) wsum[tid >> 5] = v;
    __syncthreads();
    if (tid == 0) {
        float s = 0.f;
#pragma unroll
        for (int i = 0; i < RENDER_TPB / 32; i++) s += wsum[i];
        g_part[bid] = s;
        __threadfence();
        unsigned old = atomicAdd(&g_cnt, 1u);
        s_last = (old == RENDER_BLKS - 1) ? 1 : 0;
    }
    __syncthreads();

    // ---- last block: deterministic fixed-order final reduction ----
    if (s_last) {
        double a = 0.0;
        for (int i = tid; i < RENDER_BLKS; i += RENDER_TPB)
            a += (double)__ldcg(&g_part[i]);
        sd[tid] = a;
        __syncthreads();
#pragma unroll
        for (int s = RENDER_TPB / 2; s > 0; s >>= 1) {
            if (tid < s) sd[tid] += sd[tid + s];
            __syncthreads();
        }
        if (tid == 0) {
            out[0] = (float)(sd[0] / (double)((size_t)BB * HWSZ));
            g_cnt = 0;   // self-reset for next graph replay
        }
    }
}

// ---------------- launcher --------------------------------------------------
extern "C" void kernel_launch(void* const* d_in, const int* in_sizes, int n_in,
                              void* d_out, int out_size) {
    const float* pred   = (const float*)d_in[0];  // (8,1,384,384)
    const float* nodes  = (const float*)d_in[1];  // (8,96,2)
    const float* widths = (const float*)d_in[2];  // (8,96)
    const float* fltr   = (const float*)d_in[3];  // (2,1,7,7)
    float* out = (float*)d_out;

    dim3 cgrid(WW / TILE, HH / TILE, BB);
    dim3 cblk(TILE, TILE);
    conv_kernel<<<cgrid, cblk>>>(pred, fltr);

    snake_kernel<<<BB, 128>>>(nodes, widths);

    dim3 rgrid(TILES_X, TILES_Y, BB);
    render_kernel<<<rgrid, RENDER_TPB>>>(pred, out);
}

// round 3
// speedup vs baseline: 2.8413x; 1.1704x over previous
#include <cuda_runtime.h>
#include <math.h>

// Problem constants
#define BB      8
#define HH      384
#define WW      384
#define NN      96
#define NSEG    (NN - 1)
#define HWSZ    (HH * WW)
#define STEPSZ  0.1f
#define ALPHA_C 0.01f
#define BETA_C  0.01f
#define NSTEPS  50
#define NSTEPS_W 10
#define DMAX_C  15.0f
#define EXTF    10.0f

// Render: 16x16 pixel tiles, 256 threads, 1 px/thread
#define TDIM          16
#define RENDER_TPB    256
#define TILES_X       (WW / TDIM)              // 24
#define TILES_Y       (HH / TDIM)              // 24
#define BLKS_PER_IMG  (TILES_X * TILES_Y)      // 576
#define RENDER_BLKS   (BB * BLKS_PER_IMG)      // 4608
#define TILE_RAD      10.80f

// ---------------- device scratch ----------------
__device__ float  g_g [BB * 2 * HWSZ];    // gimg  * 10
__device__ float  g_gw[BB * 2 * HWSZ];    // gimgW * 10
__device__ float4 g_segs[BB * NSEG * 3];  // per-segment data
__device__ float  g_part[RENDER_BLKS];
__device__ unsigned int g_cnt = 0;

// ---------------- kernel 1: separable 7x7 conv (2 filters) on x and |x| ----
// fy = outer(dg, g), fx = outer(g, dg); recover 1D factors from fltr[0]:
//   dg[i] = sum_j fy[i,j]   (since sum(g)   = 1)
//   g[j]  = sum_i |fy[i,j]| (since sum|dg|  = 1)
#define CT   32            // output tile (32x32)
#define CRAW 38            // CT + 6
#define CS   41            // smem row stride (odd -> conflict-free windows)

__global__ void __launch_bounds__(256)
conv_kernel(const float* __restrict__ pred, const float* __restrict__ fltr) {
    __shared__ float s_raw[CRAW * CS];
    __shared__ float s_pdg[CT * CS];
    __shared__ float s_pg [CT * CS];
    __shared__ float s_adg[CT * CS];
    __shared__ float s_ag [CT * CS];
    __shared__ float s_g1[7], s_dg1[7];

    const int b   = blockIdx.z;
    const int x0  = blockIdx.x * CT, y0 = blockIdx.y * CT;
    const int tid = threadIdx.x;

    // factor extraction (redundant per block; L1-cached loads)
    if (tid < 7) {
        float sg = 0.f, sd = 0.f;
#pragma unroll
        for (int k = 0; k < 7; k++) {
            sg += fabsf(fltr[k * 7 + tid]);   // column sum of |fy| -> g
            sd += fltr[tid * 7 + k];          // row sum of fy     -> dg
        }
        s_g1[tid] = sg;
        s_dg1[tid] = sd;
    }

    // stage raw input tile (38x38, zero-padded SAME)
    const float* img = pred + (size_t)b * HWSZ;
    for (int i = tid; i < CRAW * CRAW; i += 256) {
        int sy = i / CRAW, sx = i % CRAW;
        int gy = y0 + sy - 3, gx = x0 + sx - 3;
        float v = 0.0f;
        if (gy >= 0 && gy < HH && gx >= 0 && gx < WW) v = img[gy * WW + gx];
        s_raw[sy * CS + sx] = v;
    }
    __syncthreads();

    float rg[7], rdg[7];
#pragma unroll
    for (int k = 0; k < 7; k++) { rg[k] = s_g1[k]; rdg[k] = s_dg1[k]; }

    // pass 1: vertical correlation with dg and g, on pred and |pred|
    for (int i = tid; i < CT * CRAW; i += 256) {
        int r = i / CRAW, c = i % CRAW;
        float pdg = 0.f, pg = 0.f, adg = 0.f, ag = 0.f;
#pragma unroll
        for (int k = 0; k < 7; k++) {
            float v = s_raw[(r + k) * CS + c];
            float a = fabsf(v);
            pdg = fmaf(rdg[k], v, pdg);
            pg  = fmaf(rg[k],  v, pg);
            adg = fmaf(rdg[k], a, adg);
            ag  = fmaf(rg[k],  a, ag);
        }
        s_pdg[r * CS + c] = pdg;
        s_pg [r * CS + c] = pg;
        s_adg[r * CS + c] = adg;
        s_ag [r * CS + c] = ag;
    }
    __syncthreads();

    // pass 2: horizontal correlation; 4 consecutive output px per thread
    const int r  = tid >> 3;          // 0..31
    const int cb = (tid & 7) * 4;     // 0,4,...,28
    float wpd[10], wpg[10], wad[10], wag[10];
#pragma unroll
    for (int j = 0; j < 10; j++) {
        wpd[j] = s_pdg[r * CS + cb + j];
        wpg[j] = s_pg [r * CS + cb + j];
        wad[j] = s_adg[r * CS + cb + j];
        wag[j] = s_ag [r * CS + cb + j];
    }
    float fy0[4], fx0[4], fy1[4], fx1[4];
#pragma unroll
    for (int u = 0; u < 4; u++) {
        float a = 0.f, bz = 0.f, c = 0.f, d = 0.f;
#pragma unroll
        for (int k = 0; k < 7; k++) {
            a = fmaf(rg[k],  wpd[u + k], a);   // pred (x) fy
            bz= fmaf(rdg[k], wpg[u + k], bz);  // pred (x) fx
            c = fmaf(rg[k],  wad[u + k], c);   // |pred| (x) fy
            d = fmaf(rdg[k], wag[u + k], d);   // |pred| (x) fx
        }
        fy0[u] = a * EXTF; fx0[u] = bz * EXTF;
        fy1[u] = c * EXTF; fx1[u] = d * EXTF;
    }
    const size_t base = (size_t)b * 2 * HWSZ + (size_t)(y0 + r) * WW + (x0 + cb);
    *(float4*)(g_g  + base)        = make_float4(fy0[0], fy0[1], fy0[2], fy0[3]);
    *(float4*)(g_g  + base + HWSZ) = make_float4(fx0[0], fx0[1], fx0[2], fx0[3]);
    *(float4*)(g_gw + base)        = make_float4(fy1[0], fy1[1], fy1[2], fy1[3]);
    *(float4*)(g_gw + base + HWSZ) = make_float4(fx1[0], fx1[1], fx1[2], fx1[3]);
}

// ---------------- bilinear interp of 2-channel image ----------------------
__device__ __forceinline__ void interp2(const float* __restrict__ img,
                                        float py, float px,
                                        float& v0, float& v1) {
    float y = fminf(fmaxf(py, 0.0f), (float)(HH - 1));
    float x = fminf(fmaxf(px, 0.0f), (float)(WW - 1));
    float y0f = floorf(y), x0f = floorf(x);
    int y0 = (int)y0f, x0 = (int)x0f;
    int y1 = min(y0 + 1, HH - 1);
    int x1 = min(x0 + 1, WW - 1);
    float wy = y - y0f, wx = x - x0f;
    float w00 = (1.0f - wy) * (1.0f - wx);
    float w01 = (1.0f - wy) * wx;
    float w10 = wy * (1.0f - wx);
    float w11 = wy * wx;
    const float* c0 = img;
    const float* c1 = img + HWSZ;
    int i00 = y0 * WW + x0, i01 = y0 * WW + x1;
    int i10 = y1 * WW + x0, i11 = y1 * WW + x1;
    v0 = c0[i00] * w00 + c0[i01] * w01 + c0[i10] * w10 + c0[i11] * w11;
    v1 = c1[i00] * w00 + c1[i01] * w01 + c1[i10] * w10 + c1[i11] * w11;
}

// ---------------- kernel 2: snake evolution + width fit + segment precompute
__global__ void snake_kernel(const float* __restrict__ nodes,
                             const float* __restrict__ widths) {
    const int b = blockIdx.x;
    const int i = threadIdx.x;
    const bool act = (i < NN);

    __shared__ float xs [NN][2];
    __shared__ float d2s[NN][2];
    __shared__ float wsh[NN];

    const float* g  = g_g  + (size_t)b * 2 * HWSZ;
    const float* gw = g_gw + (size_t)b * 2 * HWSZ;

    float xy = 0.f, xx = 0.f;
    if (act) {
        xy = nodes[((size_t)b * NN + i) * 2 + 0];
        xx = nodes[((size_t)b * NN + i) * 2 + 1];
        xs[i][0] = xy; xs[i][1] = xx;
    }
    __syncthreads();

    for (int s = 0; s < NSTEPS; s++) {
        float fe0 = 0.f, fe1 = 0.f, d20 = 0.f, d21 = 0.f;
        if (act) {
            interp2(g, xy, xx, fe0, fe1);
            int im = max(i - 1, 0), ip = min(i + 1, NN - 1);
            d20 = xs[im][0] - 2.0f * xy + xs[ip][0];
            d21 = xs[im][1] - 2.0f * xx + xs[ip][1];
            d2s[i][0] = d20; d2s[i][1] = d21;
        }
        __syncthreads();
        if (act) {
            int im = max(i - 1, 0), ip = min(i + 1, NN - 1);
            float d40 = d2s[im][0] - 2.0f * d20 + d2s[ip][0];
            float d41 = d2s[im][1] - 2.0f * d21 + d2s[ip][1];
            xy += STEPSZ * (ALPHA_C * d20 - BETA_C * d40 + fe0);
            xx += STEPSZ * (ALPHA_C * d21 - BETA_C * d41 + fe1);
            xs[i][0] = xy; xs[i][1] = xx;
        }
        __syncthreads();
    }

    if (act) {
        float t0, t1;
        if (i == 0)            { t0 = xs[1][0] - xs[0][0];           t1 = xs[1][1] - xs[0][1]; }
        else if (i == NN - 1)  { t0 = xs[NN-1][0] - xs[NN-2][0];     t1 = xs[NN-1][1] - xs[NN-2][1]; }
        else                   { t0 = 0.5f * (xs[i+1][0] - xs[i-1][0]); t1 = 0.5f * (xs[i+1][1] - xs[i-1][1]); }
        float n0 = -t1, n1 = t0;
        float nrm = sqrtf(n0 * n0 + n1 * n1) + 1e-6f;
        n0 /= nrm; n1 /= nrm;

        float w = widths[(size_t)b * NN + i];
        for (int s = 0; s < NSTEPS_W; s++) {
            float gp0, gp1, gm0, gm1;
            interp2(gw, xy + w * n0, xx + w * n1, gp0, gp1);
            interp2(gw, xy - w * n0, xx - w * n1, gm0, gm1);
            float f = 0.5f * ((gp0 * n0 + gp1 * n1) - (gm0 * n0 + gm1 * n1));
            w = fmaxf(w + STEPSZ * f, 0.5f);
        }
        wsh[i] = w;
    }
    __syncthreads();

    if (i < NSEG) {
        float ay = xs[i][0],   ax = xs[i][1];
        float by = xs[i+1][0], bx = xs[i+1][1];
        float aby = by - ay, abx = bx - ax;
        float den = aby * aby + abx * abx + 1e-8f;
        float aab = ay * aby + ax * abx;
        float a2  = ay * ay + ax * ax;
        float wsg = 0.5f * (wsh[i] + wsh[i + 1]);
        float4* sp = g_segs + ((size_t)b * NSEG + i) * 3;
        sp[0] = make_float4(aby, abx, aab, 1.0f / den);
        sp[1] = make_float4(den, -2.0f * ay, -2.0f * ax, a2);
        sp[2] = make_float4(wsg, 0.f, 0.f, 0.f);
    }
}

// ---------------- kernel 3: culled render + loss + fused final reduction ---
__global__ void __launch_bounds__(RENDER_TPB)
render_kernel(const float* __restrict__ pred, float* __restrict__ out) {
    __shared__ float4 ksA[NSEG];
    __shared__ float4 ksB[NSEG];
    __shared__ float  ksW[NSEG];
    __shared__ int    s_nk;
    __shared__ int    s_last;
    __shared__ float  wsum[RENDER_TPB / 32];
    __shared__ double sd[RENDER_TPB];

    const int tid = threadIdx.x;
    const int bx = blockIdx.x, by = blockIdx.y, b = blockIdx.z;
    const int bid = (b * TILES_Y + by) * TILES_X + bx;

    if (tid == 0) s_nk = 0;
    __syncthreads();

    const float cy = (float)(by * TDIM) + 7.5f;
    const float cx = (float)(bx * TDIM) + 7.5f;
    if (tid < NSEG) {
        const float4* sp = g_segs + ((size_t)b * NSEG + tid) * 3;
        float4 qa = sp[0];
        float4 qb = sp[1];
        float  wsg = sp[2].x;
        float dotpa = fmaf(cy, qa.x, fmaf(cx, qa.y, -qa.z));
        float t = fminf(fmaxf(dotpa * qa.w, 0.0f), 1.0f);
        float pa2 = fmaf(cy, cy, cx * cx) + fmaf(cy, qb.y, fmaf(cx, qb.z, qb.w));
        float dd = fmaf(t, fmaf(t, qb.x, -2.0f * dotpa), pa2);
        float dc = sqrtf(fmaxf(dd, 0.0f));
        if (dc - wsg <= DMAX_C + TILE_RAD) {
            int slot = atomicAdd(&s_nk, 1);
            ksA[slot] = qa;
            ksB[slot] = qb;
            ksW[slot] = wsg;
        }
    }
    __syncthreads();
    const int nk = s_nk;

    const int py = by * TDIM + (tid >> 4);
    const int px = bx * TDIM + (tid & 15);
    const float fy = (float)py;
    const float fx = (float)px;
    const float p2 = fy * fy + fx * fx;

    float m = 3.0e38f;
    for (int s = 0; s < nk; s++) {
        float4 qa = ksA[s];
        float4 qb = ksB[s];
        float dotpa = fmaf(fy, qa.x, fmaf(fx, qa.y, -qa.z));
        float t = fminf(fmaxf(dotpa * qa.w, 0.0f), 1.0f);
        float pa2 = p2 + fmaf(fy, qb.y, fmaf(fx, qb.z, qb.w));
        float dd = fmaf(t, fmaf(t, qb.x, -2.0f * dotpa), pa2);
        float d = sqrtf(fmaxf(dd, 0.0f));
        m = fminf(m, d - ksW[s]);
    }
    float dmap = fminf(fmaxf(m, 0.0f), DMAX_C);
    float diff = pred[(size_t)b * HWSZ + (size_t)py * WW + px] - dmap;
    float v = diff * diff;

#pragma unroll
    for (int o = 16; o > 0; o >>= 1) v += __shfl_down_sync(0xffffffffu, v, o);
    if ((tid & 31) == 0) wsum[tid >> 5] = v;
    __syncthreads();
    if (tid == 0) {
        float s = 0.f;
#pragma unroll
        for (int i = 0; i < RENDER_TPB / 32; i++) s += wsum[i];
        g_part[bid] = s;
        __threadfence();
        unsigned old = atomicAdd(&g_cnt, 1u);
        s_last = (old == RENDER_BLKS - 1) ? 1 : 0;
    }
    __syncthreads();

    if (s_last) {
        double a = 0.0;
        for (int i = tid; i < RENDER_BLKS; i += RENDER_TPB)
            a += (double)__ldcg(&g_part[i]);
        sd[tid] = a;
        __syncthreads();
#pragma unroll
        for (int s = RENDER_TPB / 2; s > 0; s >>= 1) {
            if (tid < s) sd[tid] += sd[tid + s];
            __syncthreads();
        }
        if (tid == 0) {
            out[0] = (float)(sd[0] / (double)((size_t)BB * HWSZ));
            g_cnt = 0;
        }
    }
}

// ---------------- launcher --------------------------------------------------
extern "C" void kernel_launch(void* const* d_in, const int* in_sizes, int n_in,
                              void* d_out, int out_size) {
    const float* pred   = (const float*)d_in[0];
    const float* nodes  = (const float*)d_in[1];
    const float* widths = (const float*)d_in[2];
    const float* fltr   = (const float*)d_in[3];
    float* out = (float*)d_out;

    dim3 cgrid(WW / CT, HH / CT, BB);
    conv_kernel<<<cgrid, 256>>>(pred, fltr);

    snake_kernel<<<BB, 128>>>(nodes, widths);

    dim3 rgrid(TILES_X, TILES_Y, BB);
    render_kernel<<<rgrid, RENDER_TPB>>>(pred, out);
}